// round 8
// baseline (speedup 1.0000x reference)
#include <cuda_runtime.h>
#include <cuda_bf16.h>
#include <cstdint>

#define N_NODES 100000
#define N_EDGES 800000
#define F 128
#define HID 128
#define PITCH 136            // bf16 per row in shared tiles (conflict-free LDSM)
#define TSZ (128 * PITCH)
#define TILES (N_EDGES / 128)
#define NT_TILES ((N_NODES + 127) / 128)
#define GRID 148

// Precomputed per-node tables: A = h @ W1[0:128,:] + b1,  B = h @ W1[128:256,:]
__device__ float d_AB[2u * N_NODES * F];

// ---------------------------------------------------------------------------
__device__ __forceinline__ void mma_bf16(float* c, const uint32_t* a, const uint32_t* b) {
    asm volatile(
        "mma.sync.aligned.m16n8k16.row.col.f32.bf16.bf16.f32 "
        "{%0,%1,%2,%3}, {%4,%5,%6,%7}, {%8,%9}, {%0,%1,%2,%3};\n"
        : "+f"(c[0]), "+f"(c[1]), "+f"(c[2]), "+f"(c[3])
        : "r"(a[0]), "r"(a[1]), "r"(a[2]), "r"(a[3]), "r"(b[0]), "r"(b[1]));
}

__device__ __forceinline__ void ldsm4(uint32_t* r, uint32_t addr) {
    asm volatile("ldmatrix.sync.aligned.m8n8.x4.shared.b16 {%0,%1,%2,%3}, [%4];"
                 : "=r"(r[0]), "=r"(r[1]), "=r"(r[2]), "=r"(r[3]) : "r"(addr));
}

__device__ __forceinline__ void split_bf16(float x, __nv_bfloat16& hi, __nv_bfloat16& lo) {
    hi = __float2bfloat16(x);
    lo = __float2bfloat16(x - __bfloat162float(hi));
}

__device__ __forceinline__ uint32_t pack2(__nv_bfloat16 a, __nv_bfloat16 b) {
    __nv_bfloat162 t = __halves2bfloat162(a, b);
    return *(uint32_t*)&t;
}

__device__ __forceinline__ uint32_t smem_u32(const void* p) {
    uint32_t a;
    asm("{ .reg .u64 t; cvta.to.shared.u64 t, %1; cvt.u32.u64 %0, t; }" : "=r"(a) : "l"(p));
    return a;
}

// Per-lane LDSM byte offsets within a [row][PITCH] bf16 tile.
__device__ __forceinline__ uint32_t ldsmA_off(int lane) {
    return (uint32_t)(((lane & 15) * PITCH + ((lane >> 4) * 8)) * 2);
}
__device__ __forceinline__ uint32_t ldsmB_off(int lane) {
    return (uint32_t)((((lane & 7) + ((lane & 16) >> 1)) * PITCH + ((lane & 8) ? 8 : 0)) * 2);
}

// ---------------------------------------------------------------------------
// Kernel 1: node GEMM — unchanged from R7 (384 thr, 8 consumer warps).
// ---------------------------------------------------------------------------
__global__ void __launch_bounds__(384, 1)
node_kernel(const float* __restrict__ h,
            const float* __restrict__ W1,
            const float* __restrict__ b1) {
    extern __shared__ __nv_bfloat16 smb[];
    __nv_bfloat16* w_hi = smb;
    __nv_bfloat16* w_lo = smb + TSZ;
    __nv_bfloat16* xbuf = smb + 2 * TSZ;

    __shared__ float s_b1[128];

    const int tid  = threadIdx.x;
    const int lane = tid & 31;
    const int part = blockIdx.y;

    const float* Wp = W1 + part * F * HID;
    for (int idx = tid; idx < 128 * 128; idx += 384) {
        int k = idx >> 7, n = idx & 127;
        float w = Wp[idx];
        __nv_bfloat16 wh, wl;
        split_bf16(w, wh, wl);
        w_hi[n * PITCH + k] = wh;
        w_lo[n * PITCH + k] = wl;
    }
    if (tid < 128) s_b1[tid] = (part == 0) ? b1[tid] : 0.f;
    __syncthreads();

    const bool is_consumer = tid < 256;
    const int  ptid = tid - 256;

    const float4* h4 = (const float4*)h;
    auto fill = [&](int buf, int t) {
        __nv_bfloat16* xh = xbuf + (2 * buf) * TSZ;
        __nv_bfloat16* xl = xbuf + (2 * buf + 1) * TSZ;
        const int r0 = t * 128;
        #pragma unroll
        for (int i = 0; i < 32; i++) {
            int lin = ptid + 128 * i;
            int e = lin >> 5, v = lin & 31;
            int r = r0 + e;
            float4 a = make_float4(0.f, 0.f, 0.f, 0.f);
            if (r < N_NODES) a = h4[(size_t)r * 32 + v];
            __nv_bfloat16 h0, h1, h2, h3, l0, l1, l2, l3;
            split_bf16(a.x, h0, l0); split_bf16(a.y, h1, l1);
            split_bf16(a.z, h2, l2); split_bf16(a.w, h3, l3);
            int base = e * PITCH + v * 4;
            *(uint2*)&xh[base] = make_uint2(pack2(h0, h1), pack2(h2, h3));
            *(uint2*)&xl[base] = make_uint2(pack2(l0, l1), pack2(l2, l3));
        }
    };

    if (!is_consumer) fill(0, blockIdx.x);
    __syncthreads();

    const int warp = tid >> 5;
    const int g    = lane >> 2;
    const int tig  = lane & 3;
    const int wm   = warp & 3;
    const int wn   = warp >> 2;

    const uint32_t offA = ldsmA_off(lane) + (uint32_t)(wm * 32 * PITCH * 2);
    const uint32_t offB = ldsmB_off(lane) + (uint32_t)(wn * 64 * PITCH * 2);
    const uint32_t wh_a = smem_u32(w_hi) + offB;
    const uint32_t wl_a = smem_u32(w_lo) + offB;

    float* table = d_AB + (size_t)part * N_NODES * F;

    int s = 0;
    for (int t = blockIdx.x; t < NT_TILES; t += GRID, s++) {
        const int buf = s & 1;
        if (is_consumer) {
            const uint32_t xh_a = smem_u32(xbuf + (2 * buf) * TSZ) + offA;
            const uint32_t xl_a = smem_u32(xbuf + (2 * buf + 1) * TSZ) + offA;

            float acc[2][8][4];
            #pragma unroll
            for (int mt = 0; mt < 2; mt++)
                #pragma unroll
                for (int nt = 0; nt < 8; nt++)
                    #pragma unroll
                    for (int q = 0; q < 4; q++) acc[mt][nt][q] = 0.f;

            #pragma unroll
            for (int ks = 0; ks < 8; ks++) {
                const uint32_t kb = ks * 32;

                uint32_t a_hi[2][4], a_lo[2][4];
                #pragma unroll
                for (int mt = 0; mt < 2; mt++) {
                    ldsm4(a_hi[mt], xh_a + mt * (16 * PITCH * 2) + kb);
                    ldsm4(a_lo[mt], xl_a + mt * (16 * PITCH * 2) + kb);
                }

                uint32_t b_hi[8][2], b_lo[8][2];
                #pragma unroll
                for (int np = 0; np < 4; np++) {
                    ldsm4(&b_hi[2 * np][0], wh_a + np * (16 * PITCH * 2) + kb);
                    ldsm4(&b_lo[2 * np][0], wl_a + np * (16 * PITCH * 2) + kb);
                }

                #pragma unroll
                for (int mt = 0; mt < 2; mt++)
                    #pragma unroll
                    for (int nt = 0; nt < 8; nt++) {
                        mma_bf16(acc[mt][nt], a_hi[mt], b_hi[nt]);
                        mma_bf16(acc[mt][nt], a_hi[mt], b_lo[nt]);
                        mma_bf16(acc[mt][nt], a_lo[mt], b_hi[nt]);
                    }
            }

            const int r_base = t * 128 + wm * 32 + g;
            #pragma unroll
            for (int mt = 0; mt < 2; mt++) {
                #pragma unroll
                for (int r = 0; r < 2; r++) {
                    int row = r_base + mt * 16 + r * 8;
                    if (row < N_NODES) {
                        float* rp = table + (size_t)row * 128 + wn * 64;
                        #pragma unroll
                        for (int nt = 0; nt < 8; nt++) {
                            int c = nt * 8 + 2 * tig;
                            float2 v;
                            v.x = acc[mt][nt][2 * r]     + s_b1[wn * 64 + c];
                            v.y = acc[mt][nt][2 * r + 1] + s_b1[wn * 64 + c + 1];
                            *(float2*)(rp + c) = v;
                        }
                    }
                }
            }
        } else {
            int tn = t + GRID;
            if (tn < NT_TILES) fill(buf ^ 1, tn);
        }
        __syncthreads();
    }
}

// ---------------------------------------------------------------------------
// Kernel 2: edge kernel — 256 threads: 4 consumer warps (64x64 tiles, 2x2),
// 4 producer warps. Bigger warp tiles cut LDSM crossbar traffic 33%;
// 256-thread block lifts the per-thread register cap to 256 (acc=128 fits).
// ---------------------------------------------------------------------------
__global__ void __launch_bounds__(256, 1)
edge_kernel(const int* __restrict__ src,
            const int* __restrict__ dst,
            const float* __restrict__ W2,
            const float* __restrict__ b2,
            const float* __restrict__ W3,
            const float* __restrict__ b3,
            float* __restrict__ out) {
    extern __shared__ __nv_bfloat16 smb[];
    __nv_bfloat16* w_hi = smb;
    __nv_bfloat16* w_lo = smb + TSZ;
    __nv_bfloat16* xbuf = smb + 2 * TSZ;

    __shared__ float s_b2[128];
    __shared__ float s_w3[256];
    __shared__ float s_b3[2];
    __shared__ float s_part[2][128][2];

    const int tid  = threadIdx.x;
    const int lane = tid & 31;

    for (int idx = tid; idx < 128 * 128; idx += 256) {
        int k = idx >> 7, n = idx & 127;
        float w = W2[idx];
        __nv_bfloat16 wh, wl;
        split_bf16(w, wh, wl);
        w_hi[n * PITCH + k] = wh;
        w_lo[n * PITCH + k] = wl;
    }
    if (tid < 128) s_b2[tid] = b2[tid];
    s_w3[tid] = W3[tid];
    if (tid < 2) s_b3[tid] = b3[tid];
    __syncthreads();

    const float4* A4 = (const float4*)d_AB;
    const float4* B4 = (const float4*)(d_AB + (size_t)N_NODES * F);
    const bool is_consumer = tid < 128;
    const int  ptid = tid - 128;          // producers: warps 4-7 (128 threads)

    auto fill = [&](int buf, int t) {
        __nv_bfloat16* xh = xbuf + (2 * buf) * TSZ;
        __nv_bfloat16* xl = xbuf + (2 * buf + 1) * TSZ;
        const int e0 = t * 128;
        #pragma unroll
        for (int i = 0; i < 32; i++) {
            int lin = ptid + 128 * i;
            int e = lin >> 5, v = lin & 31;
            int si = src[e0 + e], di = dst[e0 + e];
            float4 a = A4[(size_t)si * 32 + v];
            float4 b = B4[(size_t)di * 32 + v];
            float r0 = fmaxf(a.x + b.x, 0.f), r1 = fmaxf(a.y + b.y, 0.f);
            float r2 = fmaxf(a.z + b.z, 0.f), r3 = fmaxf(a.w + b.w, 0.f);
            __nv_bfloat16 h0, h1, h2, h3, l0, l1, l2, l3;
            split_bf16(r0, h0, l0); split_bf16(r1, h1, l1);
            split_bf16(r2, h2, l2); split_bf16(r3, h3, l3);
            int base = e * PITCH + v * 4;
            *(uint2*)&xh[base] = make_uint2(pack2(h0, h1), pack2(h2, h3));
            *(uint2*)&xl[base] = make_uint2(pack2(l0, l1), pack2(l2, l3));
        }
    };

    if (!is_consumer) fill(0, blockIdx.x);
    __syncthreads();

    const int warp = tid >> 5;            // consumer warps 0-3
    const int g    = lane >> 2;
    const int tig  = lane & 3;
    const int wm   = warp & 1;            // row half (64 rows)
    const int wn   = warp >> 1;           // col half (64 cols)

    const uint32_t offA = ldsmA_off(lane) + (uint32_t)(wm * 64 * PITCH * 2);
    const uint32_t offB = ldsmB_off(lane) + (uint32_t)(wn * 64 * PITCH * 2);
    const uint32_t wh_a = smem_u32(w_hi) + offB;
    const uint32_t wl_a = smem_u32(w_lo) + offB;

    int s = 0;
    for (int t = blockIdx.x; t < TILES; t += GRID, s++) {
        const int buf = s & 1;
        if (is_consumer) {
            const uint32_t xh_a = smem_u32(xbuf + (2 * buf) * TSZ) + offA;
            const uint32_t xl_a = smem_u32(xbuf + (2 * buf + 1) * TSZ) + offA;

            float acc[4][8][4];
            #pragma unroll
            for (int mt = 0; mt < 4; mt++)
                #pragma unroll
                for (int nt = 0; nt < 8; nt++)
                    #pragma unroll
                    for (int q = 0; q < 4; q++) acc[mt][nt][q] = 0.f;

            #pragma unroll
            for (int ks = 0; ks < 8; ks++) {
                const uint32_t kb = ks * 32;

                uint32_t a_hi[4][4], a_lo[4][4];
                #pragma unroll
                for (int mt = 0; mt < 4; mt++) {
                    ldsm4(a_hi[mt], xh_a + mt * (16 * PITCH * 2) + kb);
                    ldsm4(a_lo[mt], xl_a + mt * (16 * PITCH * 2) + kb);
                }

                uint32_t b_hi[8][2], b_lo[8][2];
                #pragma unroll
                for (int np = 0; np < 4; np++) {
                    ldsm4(&b_hi[2 * np][0], wh_a + np * (16 * PITCH * 2) + kb);
                    ldsm4(&b_lo[2 * np][0], wl_a + np * (16 * PITCH * 2) + kb);
                }

                #pragma unroll
                for (int mt = 0; mt < 4; mt++)
                    #pragma unroll
                    for (int nt = 0; nt < 8; nt++) {
                        mma_bf16(acc[mt][nt], a_hi[mt], b_hi[nt]);
                        mma_bf16(acc[mt][nt], a_hi[mt], b_lo[nt]);
                        mma_bf16(acc[mt][nt], a_lo[mt], b_hi[nt]);
                    }
            }

            // epilogue: bias2 + relu + layer3 partials
            float p[4][2][2];
            #pragma unroll
            for (int mt = 0; mt < 4; mt++)
                #pragma unroll
                for (int r = 0; r < 2; r++) { p[mt][r][0] = 0.f; p[mt][r][1] = 0.f; }

            #pragma unroll
            for (int nt = 0; nt < 8; nt++) {
                int c0 = wn * 64 + nt * 8 + 2 * tig;
                float bb0 = s_b2[c0], bb1 = s_b2[c0 + 1];
                float w300 = s_w3[c0 * 2],       w310 = s_w3[c0 * 2 + 1];
                float w301 = s_w3[(c0 + 1) * 2], w311 = s_w3[(c0 + 1) * 2 + 1];
                #pragma unroll
                for (int mt = 0; mt < 4; mt++) {
                    float x00 = fmaxf(acc[mt][nt][0] + bb0, 0.f);
                    float x01 = fmaxf(acc[mt][nt][1] + bb1, 0.f);
                    float x10 = fmaxf(acc[mt][nt][2] + bb0, 0.f);
                    float x11 = fmaxf(acc[mt][nt][3] + bb1, 0.f);
                    p[mt][0][0] = fmaf(x00, w300, fmaf(x01, w301, p[mt][0][0]));
                    p[mt][0][1] = fmaf(x00, w310, fmaf(x01, w311, p[mt][0][1]));
                    p[mt][1][0] = fmaf(x10, w300, fmaf(x11, w301, p[mt][1][0]));
                    p[mt][1][1] = fmaf(x10, w310, fmaf(x11, w311, p[mt][1][1]));
                }
            }

            #pragma unroll
            for (int mt = 0; mt < 4; mt++)
                #pragma unroll
                for (int r = 0; r < 2; r++)
                    #pragma unroll
                    for (int o = 0; o < 2; o++) {
                        float v = p[mt][r][o];
                        v += __shfl_xor_sync(0xffffffffu, v, 1);
                        v += __shfl_xor_sync(0xffffffffu, v, 2);
                        p[mt][r][o] = v;
                    }

            if (tig == 0) {
                #pragma unroll
                for (int mt = 0; mt < 4; mt++) {
                    int r0 = wm * 64 + mt * 16 + g;
                    s_part[wn][r0][0]     = p[mt][0][0];
                    s_part[wn][r0][1]     = p[mt][0][1];
                    s_part[wn][r0 + 8][0] = p[mt][1][0];
                    s_part[wn][r0 + 8][1] = p[mt][1][1];
                }
            }
            asm volatile("bar.sync 1, 128;" ::: "memory");
            // 128 consumer threads each write one edge's float2
            float2 o2;
            o2.x = s_part[0][tid][0] + s_part[1][tid][0] + s_b3[0];
            o2.y = s_part[0][tid][1] + s_part[1][tid][1] + s_b3[1];
            *(float2*)(out + ((size_t)t * 128 + tid) * 2) = o2;
        } else {
            int tn = t + GRID;
            if (tn < TILES) fill(buf ^ 1, tn);
        }
        __syncthreads();
    }
}

// ---------------------------------------------------------------------------
extern "C" void kernel_launch(void* const* d_in, const int* in_sizes, int n_in,
                              void* d_out, int out_size) {
    const float* h   = (const float*)d_in[0];
    const int*   src = (const int*)d_in[1];
    const int*   dst = (const int*)d_in[2];
    const float* W1  = (const float*)d_in[3];
    const float* b1  = (const float*)d_in[4];
    const float* W2  = (const float*)d_in[5];
    const float* b2  = (const float*)d_in[6];
    const float* W3  = (const float*)d_in[7];
    const float* b3  = (const float*)d_in[8];
    float* out = (float*)d_out;

    const int smem = 6 * TSZ * (int)sizeof(__nv_bfloat16);  // 208896
    cudaFuncSetAttribute(node_kernel, cudaFuncAttributeMaxDynamicSharedMemorySize, smem);
    cudaFuncSetAttribute(edge_kernel, cudaFuncAttributeMaxDynamicSharedMemorySize, smem);

    node_kernel<<<dim3(GRID, 2), 384, smem>>>(h, W1, b1);
    edge_kernel<<<GRID, 256, smem>>>(src, dst, W2, b2, W3, b3, out);
}

// round 9
// speedup vs baseline: 1.0263x; 1.0263x over previous
#include <cuda_runtime.h>
#include <cuda_bf16.h>
#include <cstdint>

#define N_NODES 100000
#define N_EDGES 800000
#define F 128
#define HID 128
#define PITCH 136            // bf16 per row in shared tiles (conflict-free LDSM)
#define TSZ (128 * PITCH)
#define TILES (N_EDGES / 128)
#define NT_TILES ((N_NODES + 127) / 128)
#define GRID 148

// Precomputed per-node tables: A = h @ W1[0:128,:] + b1,  B = h @ W1[128:256,:]
__device__ float d_AB[2u * N_NODES * F];

// ---------------------------------------------------------------------------
__device__ __forceinline__ void mma_bf16(float* c, const uint32_t* a, const uint32_t* b) {
    asm volatile(
        "mma.sync.aligned.m16n8k16.row.col.f32.bf16.bf16.f32 "
        "{%0,%1,%2,%3}, {%4,%5,%6,%7}, {%8,%9}, {%0,%1,%2,%3};\n"
        : "+f"(c[0]), "+f"(c[1]), "+f"(c[2]), "+f"(c[3])
        : "r"(a[0]), "r"(a[1]), "r"(a[2]), "r"(a[3]), "r"(b[0]), "r"(b[1]));
}

__device__ __forceinline__ void ldsm4(uint32_t* r, uint32_t addr) {
    asm volatile("ldmatrix.sync.aligned.m8n8.x4.shared.b16 {%0,%1,%2,%3}, [%4];"
                 : "=r"(r[0]), "=r"(r[1]), "=r"(r[2]), "=r"(r[3]) : "r"(addr));
}

__device__ __forceinline__ void split_bf16(float x, __nv_bfloat16& hi, __nv_bfloat16& lo) {
    hi = __float2bfloat16(x);
    lo = __float2bfloat16(x - __bfloat162float(hi));
}

__device__ __forceinline__ uint32_t pack2(__nv_bfloat16 a, __nv_bfloat16 b) {
    __nv_bfloat162 t = __halves2bfloat162(a, b);
    return *(uint32_t*)&t;
}

__device__ __forceinline__ uint32_t smem_u32(const void* p) {
    uint32_t a;
    asm("{ .reg .u64 t; cvta.to.shared.u64 t, %1; cvt.u32.u64 %0, t; }" : "=r"(a) : "l"(p));
    return a;
}

// Per-lane LDSM byte offsets within a [row][PITCH] bf16 tile.
__device__ __forceinline__ uint32_t ldsmA_off(int lane) {
    return (uint32_t)(((lane & 15) * PITCH + ((lane >> 4) * 8)) * 2);
}
__device__ __forceinline__ uint32_t ldsmB_off(int lane) {
    return (uint32_t)((((lane & 7) + ((lane & 16) >> 1)) * PITCH + ((lane & 8) ? 8 : 0)) * 2);
}

// ---------------------------------------------------------------------------
// Shared consumer inner loop: 32x64 warp tile, 3-pass bf16 split,
// phase-staggered k order (kph decorrelates warp pairs on one SMSP),
// B frags loaded in two nt-halves to cut live register pressure.
// ---------------------------------------------------------------------------
__device__ __forceinline__ void consume_tile(float acc[2][8][4],
                                             uint32_t xh_a, uint32_t xl_a,
                                             uint32_t wh_a, uint32_t wl_a,
                                             int kph) {
    #pragma unroll
    for (int kk = 0; kk < 8; kk++) {
        const int ks = (kk + kph) & 7;
        const uint32_t kb = (uint32_t)ks * 32;

        uint32_t a_hi[2][4], a_lo[2][4];
        #pragma unroll
        for (int mt = 0; mt < 2; mt++) {
            ldsm4(a_hi[mt], xh_a + mt * (16 * PITCH * 2) + kb);
            ldsm4(a_lo[mt], xl_a + mt * (16 * PITCH * 2) + kb);
        }

        #pragma unroll
        for (int half = 0; half < 2; half++) {
            uint32_t b_hi[4][2], b_lo[4][2];
            #pragma unroll
            for (int np = 0; np < 2; np++) {
                ldsm4(&b_hi[2 * np][0], wh_a + (half * 2 + np) * (16 * PITCH * 2) + kb);
                ldsm4(&b_lo[2 * np][0], wl_a + (half * 2 + np) * (16 * PITCH * 2) + kb);
            }
            #pragma unroll
            for (int mt = 0; mt < 2; mt++)
                #pragma unroll
                for (int n4 = 0; n4 < 4; n4++) {
                    float* c = acc[mt][half * 4 + n4];
                    mma_bf16(c, a_hi[mt], b_hi[n4]);
                    mma_bf16(c, a_hi[mt], b_lo[n4]);
                    mma_bf16(c, a_lo[mt], b_hi[n4]);
                }
        }
    }
}

// ---------------------------------------------------------------------------
// Kernel 1: node GEMM — persistent, warp-specialized (8 consumers + 4 producers).
// grid (148, 2): y = part (A / B table).
// ---------------------------------------------------------------------------
__global__ void __launch_bounds__(384, 1)
node_kernel(const float* __restrict__ h,
            const float* __restrict__ W1,
            const float* __restrict__ b1) {
    extern __shared__ __nv_bfloat16 smb[];
    __nv_bfloat16* w_hi = smb;
    __nv_bfloat16* w_lo = smb + TSZ;
    __nv_bfloat16* xbuf = smb + 2 * TSZ;

    __shared__ float s_b1[128];

    const int tid  = threadIdx.x;
    const int lane = tid & 31;
    const int part = blockIdx.y;

    const float* Wp = W1 + part * F * HID;
    for (int idx = tid; idx < 128 * 128; idx += 384) {
        int k = idx >> 7, n = idx & 127;
        float w = Wp[idx];
        __nv_bfloat16 wh, wl;
        split_bf16(w, wh, wl);
        w_hi[n * PITCH + k] = wh;
        w_lo[n * PITCH + k] = wl;
    }
    if (tid < 128) s_b1[tid] = (part == 0) ? b1[tid] : 0.f;
    __syncthreads();

    const bool is_consumer = tid < 256;
    const int  ptid = tid - 256;

    const float4* h4 = (const float4*)h;
    auto fill = [&](int buf, int t) {
        __nv_bfloat16* xh = xbuf + (2 * buf) * TSZ;
        __nv_bfloat16* xl = xbuf + (2 * buf + 1) * TSZ;
        const int r0 = t * 128;
        #pragma unroll
        for (int i = 0; i < 32; i++) {
            int lin = ptid + 128 * i;
            int e = lin >> 5, v = lin & 31;
            int r = r0 + e;
            float4 a = make_float4(0.f, 0.f, 0.f, 0.f);
            if (r < N_NODES) a = h4[(size_t)r * 32 + v];
            __nv_bfloat16 h0, h1, h2, h3, l0, l1, l2, l3;
            split_bf16(a.x, h0, l0); split_bf16(a.y, h1, l1);
            split_bf16(a.z, h2, l2); split_bf16(a.w, h3, l3);
            int base = e * PITCH + v * 4;
            *(uint2*)&xh[base] = make_uint2(pack2(h0, h1), pack2(h2, h3));
            *(uint2*)&xl[base] = make_uint2(pack2(l0, l1), pack2(l2, l3));
        }
    };

    if (!is_consumer) fill(0, blockIdx.x);
    __syncthreads();

    const int warp = tid >> 5;
    const int g    = lane >> 2;
    const int tig  = lane & 3;
    const int wm   = warp & 3;
    const int wn   = warp >> 2;
    const int kph  = ((warp >> 2) & 1) * 4;   // anti-phase the SMSP warp pairs

    const uint32_t offA = ldsmA_off(lane) + (uint32_t)(wm * 32 * PITCH * 2);
    const uint32_t offB = ldsmB_off(lane) + (uint32_t)(wn * 64 * PITCH * 2);
    const uint32_t wh_a = smem_u32(w_hi) + offB;
    const uint32_t wl_a = smem_u32(w_lo) + offB;

    float* table = d_AB + (size_t)part * N_NODES * F;

    int s = 0;
    for (int t = blockIdx.x; t < NT_TILES; t += GRID, s++) {
        const int buf = s & 1;
        if (is_consumer) {
            const uint32_t xh_a = smem_u32(xbuf + (2 * buf) * TSZ) + offA;
            const uint32_t xl_a = smem_u32(xbuf + (2 * buf + 1) * TSZ) + offA;

            float acc[2][8][4];
            #pragma unroll
            for (int mt = 0; mt < 2; mt++)
                #pragma unroll
                for (int nt = 0; nt < 8; nt++)
                    #pragma unroll
                    for (int q = 0; q < 4; q++) acc[mt][nt][q] = 0.f;

            consume_tile(acc, xh_a, xl_a, wh_a, wl_a, kph);

            const int r_base = t * 128 + wm * 32 + g;
            #pragma unroll
            for (int mt = 0; mt < 2; mt++) {
                #pragma unroll
                for (int r = 0; r < 2; r++) {
                    int row = r_base + mt * 16 + r * 8;
                    if (row < N_NODES) {
                        float* rp = table + (size_t)row * 128 + wn * 64;
                        #pragma unroll
                        for (int nt = 0; nt < 8; nt++) {
                            int c = nt * 8 + 2 * tig;
                            float2 v;
                            v.x = acc[mt][nt][2 * r]     + s_b1[wn * 64 + c];
                            v.y = acc[mt][nt][2 * r + 1] + s_b1[wn * 64 + c + 1];
                            *(float2*)(rp + c) = v;
                        }
                    }
                }
            }
        } else {
            int tn = t + GRID;
            if (tn < NT_TILES) fill(buf ^ 1, tn);
        }
        __syncthreads();
    }
}

// ---------------------------------------------------------------------------
// Kernel 2: edge kernel — persistent, warp-specialized (8 consumers + 4 producers).
// ---------------------------------------------------------------------------
__global__ void __launch_bounds__(384, 1)
edge_kernel(const int* __restrict__ src,
            const int* __restrict__ dst,
            const float* __restrict__ W2,
            const float* __restrict__ b2,
            const float* __restrict__ W3,
            const float* __restrict__ b3,
            float* __restrict__ out) {
    extern __shared__ __nv_bfloat16 smb[];
    __nv_bfloat16* w_hi = smb;
    __nv_bfloat16* w_lo = smb + TSZ;
    __nv_bfloat16* xbuf = smb + 2 * TSZ;

    __shared__ float s_b2[128];
    __shared__ float s_w3[256];
    __shared__ float s_b3[2];
    __shared__ float s_part[2][128][2];

    const int tid  = threadIdx.x;
    const int lane = tid & 31;

    for (int idx = tid; idx < 128 * 128; idx += 384) {
        int k = idx >> 7, n = idx & 127;
        float w = W2[idx];
        __nv_bfloat16 wh, wl;
        split_bf16(w, wh, wl);
        w_hi[n * PITCH + k] = wh;
        w_lo[n * PITCH + k] = wl;
    }
    if (tid < 128) s_b2[tid] = b2[tid];
    if (tid < 256) s_w3[tid] = W3[tid];
    if (tid < 2)   s_b3[tid] = b3[tid];
    __syncthreads();

    const float4* A4 = (const float4*)d_AB;
    const float4* B4 = (const float4*)(d_AB + (size_t)N_NODES * F);
    const bool is_consumer = tid < 256;
    const int  ptid = tid - 256;

    auto fill = [&](int buf, int t) {
        __nv_bfloat16* xh = xbuf + (2 * buf) * TSZ;
        __nv_bfloat16* xl = xbuf + (2 * buf + 1) * TSZ;
        const int e0 = t * 128;
        #pragma unroll
        for (int i = 0; i < 32; i++) {
            int lin = ptid + 128 * i;
            int e = lin >> 5, v = lin & 31;
            int si = src[e0 + e], di = dst[e0 + e];
            float4 a = A4[(size_t)si * 32 + v];
            float4 b = B4[(size_t)di * 32 + v];
            float r0 = fmaxf(a.x + b.x, 0.f), r1 = fmaxf(a.y + b.y, 0.f);
            float r2 = fmaxf(a.z + b.z, 0.f), r3 = fmaxf(a.w + b.w, 0.f);
            __nv_bfloat16 h0, h1, h2, h3, l0, l1, l2, l3;
            split_bf16(r0, h0, l0); split_bf16(r1, h1, l1);
            split_bf16(r2, h2, l2); split_bf16(r3, h3, l3);
            int base = e * PITCH + v * 4;
            *(uint2*)&xh[base] = make_uint2(pack2(h0, h1), pack2(h2, h3));
            *(uint2*)&xl[base] = make_uint2(pack2(l0, l1), pack2(l2, l3));
        }
    };

    if (!is_consumer) fill(0, blockIdx.x);
    __syncthreads();

    const int warp = tid >> 5;
    const int g    = lane >> 2;
    const int tig  = lane & 3;
    const int wm   = warp & 3;
    const int wn   = warp >> 2;
    const int kph  = ((warp >> 2) & 1) * 4;   // anti-phase the SMSP warp pairs

    const uint32_t offA = ldsmA_off(lane) + (uint32_t)(wm * 32 * PITCH * 2);
    const uint32_t offB = ldsmB_off(lane) + (uint32_t)(wn * 64 * PITCH * 2);
    const uint32_t wh_a = smem_u32(w_hi) + offB;
    const uint32_t wl_a = smem_u32(w_lo) + offB;

    int s = 0;
    for (int t = blockIdx.x; t < TILES; t += GRID, s++) {
        const int buf = s & 1;
        if (is_consumer) {
            const uint32_t xh_a = smem_u32(xbuf + (2 * buf) * TSZ) + offA;
            const uint32_t xl_a = smem_u32(xbuf + (2 * buf + 1) * TSZ) + offA;

            float acc[2][8][4];
            #pragma unroll
            for (int mt = 0; mt < 2; mt++)
                #pragma unroll
                for (int nt = 0; nt < 8; nt++)
                    #pragma unroll
                    for (int q = 0; q < 4; q++) acc[mt][nt][q] = 0.f;

            consume_tile(acc, xh_a, xl_a, wh_a, wl_a, kph);

            float p[2][2][2];
            #pragma unroll
            for (int mt = 0; mt < 2; mt++)
                #pragma unroll
                for (int r = 0; r < 2; r++) { p[mt][r][0] = 0.f; p[mt][r][1] = 0.f; }

            #pragma unroll
            for (int nt = 0; nt < 8; nt++) {
                int c0 = wn * 64 + nt * 8 + 2 * tig;
                float bb0 = s_b2[c0], bb1 = s_b2[c0 + 1];
                float w300 = s_w3[c0 * 2],       w310 = s_w3[c0 * 2 + 1];
                float w301 = s_w3[(c0 + 1) * 2], w311 = s_w3[(c0 + 1) * 2 + 1];
                #pragma unroll
                for (int mt = 0; mt < 2; mt++) {
                    float x00 = fmaxf(acc[mt][nt][0] + bb0, 0.f);
                    float x01 = fmaxf(acc[mt][nt][1] + bb1, 0.f);
                    float x10 = fmaxf(acc[mt][nt][2] + bb0, 0.f);
                    float x11 = fmaxf(acc[mt][nt][3] + bb1, 0.f);
                    p[mt][0][0] = fmaf(x00, w300, fmaf(x01, w301, p[mt][0][0]));
                    p[mt][0][1] = fmaf(x00, w310, fmaf(x01, w311, p[mt][0][1]));
                    p[mt][1][0] = fmaf(x10, w300, fmaf(x11, w301, p[mt][1][0]));
                    p[mt][1][1] = fmaf(x10, w310, fmaf(x11, w311, p[mt][1][1]));
                }
            }

            #pragma unroll
            for (int mt = 0; mt < 2; mt++)
                #pragma unroll
                for (int r = 0; r < 2; r++)
                    #pragma unroll
                    for (int o = 0; o < 2; o++) {
                        float v = p[mt][r][o];
                        v += __shfl_xor_sync(0xffffffffu, v, 1);
                        v += __shfl_xor_sync(0xffffffffu, v, 2);
                        p[mt][r][o] = v;
                    }

            if (tig == 0) {
                #pragma unroll
                for (int mt = 0; mt < 2; mt++) {
                    int r0 = wm * 32 + mt * 16 + g;
                    s_part[wn][r0][0]     = p[mt][0][0];
                    s_part[wn][r0][1]     = p[mt][0][1];
                    s_part[wn][r0 + 8][0] = p[mt][1][0];
                    s_part[wn][r0 + 8][1] = p[mt][1][1];
                }
            }
            asm volatile("bar.sync 1, 256;" ::: "memory");
            out[(size_t)t * 256 + tid] =
                s_part[0][tid >> 1][tid & 1] + s_part[1][tid >> 1][tid & 1] + s_b3[tid & 1];
        } else {
            int tn = t + GRID;
            if (tn < TILES) fill(buf ^ 1, tn);
        }
        __syncthreads();
    }
}

// ---------------------------------------------------------------------------
extern "C" void kernel_launch(void* const* d_in, const int* in_sizes, int n_in,
                              void* d_out, int out_size) {
    const float* h   = (const float*)d_in[0];
    const int*   src = (const int*)d_in[1];
    const int*   dst = (const int*)d_in[2];
    const float* W1  = (const float*)d_in[3];
    const float* b1  = (const float*)d_in[4];
    const float* W2  = (const float*)d_in[5];
    const float* b2  = (const float*)d_in[6];
    const float* W3  = (const float*)d_in[7];
    const float* b3  = (const float*)d_in[8];
    float* out = (float*)d_out;

    const int smem = 6 * TSZ * (int)sizeof(__nv_bfloat16);  // 208896
    cudaFuncSetAttribute(node_kernel, cudaFuncAttributeMaxDynamicSharedMemorySize, smem);
    cudaFuncSetAttribute(edge_kernel, cudaFuncAttributeMaxDynamicSharedMemorySize, smem);

    node_kernel<<<dim3(GRID, 2), 384, smem>>>(h, W1, b1);
    edge_kernel<<<GRID, 384, smem>>>(src, dst, W2, b2, W3, b3, out);
}

// round 10
// speedup vs baseline: 1.2371x; 1.2054x over previous
#include <cuda_runtime.h>
#include <cuda_bf16.h>
#include <cuda_fp16.h>
#include <cstdint>

#define N_NODES 100000
#define N_EDGES 800000
#define F 128
#define HID 128
#define PITCH 136            // elems per row in shared tiles (conflict-free LDSM)
#define TSZ (128 * PITCH)
#define TILES (N_EDGES / 128)
#define NT_TILES ((N_NODES + 127) / 128)
#define GRID 148

// Precomputed per-node tables: A = h @ W1[0:128,:] + b1,  B = h @ W1[128:256,:]
__device__ float d_AB[2u * N_NODES * F];

// ---------------------------------------------------------------------------
__device__ __forceinline__ void mma_bf16(float* c, const uint32_t* a, const uint32_t* b) {
    asm volatile(
        "mma.sync.aligned.m16n8k16.row.col.f32.bf16.bf16.f32 "
        "{%0,%1,%2,%3}, {%4,%5,%6,%7}, {%8,%9}, {%0,%1,%2,%3};\n"
        : "+f"(c[0]), "+f"(c[1]), "+f"(c[2]), "+f"(c[3])
        : "r"(a[0]), "r"(a[1]), "r"(a[2]), "r"(a[3]), "r"(b[0]), "r"(b[1]));
}

__device__ __forceinline__ void mma_f16(float* c, const uint32_t* a, const uint32_t* b) {
    asm volatile(
        "mma.sync.aligned.m16n8k16.row.col.f32.f16.f16.f32 "
        "{%0,%1,%2,%3}, {%4,%5,%6,%7}, {%8,%9}, {%0,%1,%2,%3};\n"
        : "+f"(c[0]), "+f"(c[1]), "+f"(c[2]), "+f"(c[3])
        : "r"(a[0]), "r"(a[1]), "r"(a[2]), "r"(a[3]), "r"(b[0]), "r"(b[1]));
}

__device__ __forceinline__ void ldsm4(uint32_t* r, uint32_t addr) {
    asm volatile("ldmatrix.sync.aligned.m8n8.x4.shared.b16 {%0,%1,%2,%3}, [%4];"
                 : "=r"(r[0]), "=r"(r[1]), "=r"(r[2]), "=r"(r[3]) : "r"(addr));
}

__device__ __forceinline__ void split_bf16(float x, __nv_bfloat16& hi, __nv_bfloat16& lo) {
    hi = __float2bfloat16(x);
    lo = __float2bfloat16(x - __bfloat162float(hi));
}

__device__ __forceinline__ void split_f16(float x, __half& hi, __half& lo) {
    hi = __float2half(x);
    lo = __float2half(x - __half2float(hi));
}

__device__ __forceinline__ uint32_t pack2(__nv_bfloat16 a, __nv_bfloat16 b) {
    __nv_bfloat162 t = __halves2bfloat162(a, b);
    return *(uint32_t*)&t;
}

__device__ __forceinline__ uint32_t smem_u32(const void* p) {
    uint32_t a;
    asm("{ .reg .u64 t; cvta.to.shared.u64 t, %1; cvt.u32.u64 %0, t; }" : "=r"(a) : "l"(p));
    return a;
}

// Per-lane LDSM byte offsets within a [row][PITCH] 16-bit tile.
__device__ __forceinline__ uint32_t ldsmA_off(int lane) {
    return (uint32_t)(((lane & 15) * PITCH + ((lane >> 4) * 8)) * 2);
}
__device__ __forceinline__ uint32_t ldsmB_off(int lane) {
    return (uint32_t)((((lane & 7) + ((lane & 16) >> 1)) * PITCH + ((lane & 8) ? 8 : 0)) * 2);
}

// ---------------------------------------------------------------------------
// Kernel 1: node GEMM — persistent, warp-specialized, bf16 3-pass (known good).
// grid (148, 2): y = part (A / B table).
// ---------------------------------------------------------------------------
__global__ void __launch_bounds__(384, 1)
node_kernel(const float* __restrict__ h,
            const float* __restrict__ W1,
            const float* __restrict__ b1) {
    extern __shared__ __nv_bfloat16 smb[];
    __nv_bfloat16* w_hi = smb;
    __nv_bfloat16* w_lo = smb + TSZ;
    __nv_bfloat16* xbuf = smb + 2 * TSZ;

    __shared__ float s_b1[128];

    const int tid  = threadIdx.x;
    const int lane = tid & 31;
    const int part = blockIdx.y;

    const float* Wp = W1 + part * F * HID;
    for (int idx = tid; idx < 128 * 128; idx += 384) {
        int k = idx >> 7, n = idx & 127;
        float w = Wp[idx];
        __nv_bfloat16 wh, wl;
        split_bf16(w, wh, wl);
        w_hi[n * PITCH + k] = wh;
        w_lo[n * PITCH + k] = wl;
    }
    if (tid < 128) s_b1[tid] = (part == 0) ? b1[tid] : 0.f;
    __syncthreads();

    const bool is_consumer = tid < 256;
    const int  ptid = tid - 256;

    const float4* h4 = (const float4*)h;
    auto fill = [&](int buf, int t) {
        __nv_bfloat16* xh = xbuf + (2 * buf) * TSZ;
        __nv_bfloat16* xl = xbuf + (2 * buf + 1) * TSZ;
        const int r0 = t * 128;
        #pragma unroll
        for (int i = 0; i < 32; i++) {
            int lin = ptid + 128 * i;
            int e = lin >> 5, v = lin & 31;
            int r = r0 + e;
            float4 a = make_float4(0.f, 0.f, 0.f, 0.f);
            if (r < N_NODES) a = h4[(size_t)r * 32 + v];
            __nv_bfloat16 h0, h1, h2, h3, l0, l1, l2, l3;
            split_bf16(a.x, h0, l0); split_bf16(a.y, h1, l1);
            split_bf16(a.z, h2, l2); split_bf16(a.w, h3, l3);
            int base = e * PITCH + v * 4;
            *(uint2*)&xh[base] = make_uint2(pack2(h0, h1), pack2(h2, h3));
            *(uint2*)&xl[base] = make_uint2(pack2(l0, l1), pack2(l2, l3));
        }
    };

    if (!is_consumer) fill(0, blockIdx.x);
    __syncthreads();

    const int warp = tid >> 5;
    const int g    = lane >> 2;
    const int tig  = lane & 3;
    const int wm   = warp & 3;
    const int wn   = warp >> 2;

    const uint32_t offA = ldsmA_off(lane) + (uint32_t)(wm * 32 * PITCH * 2);
    const uint32_t offB = ldsmB_off(lane) + (uint32_t)(wn * 64 * PITCH * 2);
    const uint32_t wh_a = smem_u32(w_hi) + offB;
    const uint32_t wl_a = smem_u32(w_lo) + offB;

    float* table = d_AB + (size_t)part * N_NODES * F;

    int s = 0;
    for (int t = blockIdx.x; t < NT_TILES; t += GRID, s++) {
        const int buf = s & 1;
        if (is_consumer) {
            const uint32_t xh_a = smem_u32(xbuf + (2 * buf) * TSZ) + offA;
            const uint32_t xl_a = smem_u32(xbuf + (2 * buf + 1) * TSZ) + offA;

            float acc[2][8][4];
            #pragma unroll
            for (int mt = 0; mt < 2; mt++)
                #pragma unroll
                for (int nt = 0; nt < 8; nt++)
                    #pragma unroll
                    for (int q = 0; q < 4; q++) acc[mt][nt][q] = 0.f;

            #pragma unroll
            for (int ks = 0; ks < 8; ks++) {
                const uint32_t kb = ks * 32;

                uint32_t a_hi[2][4], a_lo[2][4];
                #pragma unroll
                for (int mt = 0; mt < 2; mt++) {
                    ldsm4(a_hi[mt], xh_a + mt * (16 * PITCH * 2) + kb);
                    ldsm4(a_lo[mt], xl_a + mt * (16 * PITCH * 2) + kb);
                }

                uint32_t b_hi[8][2], b_lo[8][2];
                #pragma unroll
                for (int np = 0; np < 4; np++) {
                    ldsm4(&b_hi[2 * np][0], wh_a + np * (16 * PITCH * 2) + kb);
                    ldsm4(&b_lo[2 * np][0], wl_a + np * (16 * PITCH * 2) + kb);
                }

                #pragma unroll
                for (int mt = 0; mt < 2; mt++)
                    #pragma unroll
                    for (int nt = 0; nt < 8; nt++) {
                        mma_bf16(acc[mt][nt], a_hi[mt], b_hi[nt]);
                        mma_bf16(acc[mt][nt], a_hi[mt], b_lo[nt]);
                        mma_bf16(acc[mt][nt], a_lo[mt], b_hi[nt]);
                    }
            }

            const int r_base = t * 128 + wm * 32 + g;
            #pragma unroll
            for (int mt = 0; mt < 2; mt++) {
                #pragma unroll
                for (int r = 0; r < 2; r++) {
                    int row = r_base + mt * 16 + r * 8;
                    if (row < N_NODES) {
                        float* rp = table + (size_t)row * 128 + wn * 64;
                        #pragma unroll
                        for (int nt = 0; nt < 8; nt++) {
                            int c = nt * 8 + 2 * tig;
                            float2 v;
                            v.x = acc[mt][nt][2 * r]     + s_b1[wn * 64 + c];
                            v.y = acc[mt][nt][2 * r + 1] + s_b1[wn * 64 + c + 1];
                            *(float2*)(rp + c) = v;
                        }
                    }
                }
            }
        } else {
            int tn = t + GRID;
            if (tn < NT_TILES) fill(buf ^ 1, tn);
        }
        __syncthreads();
    }
}

// ---------------------------------------------------------------------------
// Kernel 2: edge kernel — fp16 2-pass: x in plain fp16, W2 split w_h + w_l.
// x_h*(w_h + w_l) = x_h*w exactly; dropped term x_l*w ~ 2^-12 relative.
// Per k-step: 10 LDSM (was 12), 32 HMMA (was 48).
// ---------------------------------------------------------------------------
__global__ void __launch_bounds__(384, 1)
edge_kernel(const int* __restrict__ src,
            const int* __restrict__ dst,
            const float* __restrict__ W2,
            const float* __restrict__ b2,
            const float* __restrict__ W3,
            const float* __restrict__ b3,
            float* __restrict__ out) {
    extern __shared__ __half smh[];
    __half* w_h  = smh;                  // [n][k] transposed, fp16 hi
    __half* w_l  = smh + TSZ;            // fp16 residual
    __half* xbuf = smh + 2 * TSZ;        // 2 buffers, plain fp16

    __shared__ float s_b2[128];
    __shared__ float s_w3[256];
    __shared__ float s_b3[2];
    __shared__ float s_part[2][128][2];

    const int tid  = threadIdx.x;
    const int lane = tid & 31;

    for (int idx = tid; idx < 128 * 128; idx += 384) {
        int k = idx >> 7, n = idx & 127;
        float w = W2[idx];
        __half wh, wl;
        split_f16(w, wh, wl);
        w_h[n * PITCH + k] = wh;
        w_l[n * PITCH + k] = wl;
    }
    if (tid < 128) s_b2[tid] = b2[tid];
    if (tid < 256) s_w3[tid] = W3[tid];
    if (tid < 2)   s_b3[tid] = b3[tid];
    __syncthreads();

    const float4* A4 = (const float4*)d_AB;
    const float4* B4 = (const float4*)(d_AB + (size_t)N_NODES * F);
    const bool is_consumer = tid < 256;
    const int  ptid = tid - 256;

    auto fill = [&](int buf, int t) {
        __half* x = xbuf + buf * TSZ;
        const int e0 = t * 128;
        #pragma unroll
        for (int i = 0; i < 32; i++) {
            int lin = ptid + 128 * i;
            int e = lin >> 5, v = lin & 31;
            int si = src[e0 + e], di = dst[e0 + e];
            float4 a = A4[(size_t)si * 32 + v];
            float4 b = B4[(size_t)di * 32 + v];
            __half2 p01 = __floats2half2_rn(fmaxf(a.x + b.x, 0.f), fmaxf(a.y + b.y, 0.f));
            __half2 p23 = __floats2half2_rn(fmaxf(a.z + b.z, 0.f), fmaxf(a.w + b.w, 0.f));
            int base = e * PITCH + v * 4;
            *(uint2*)&x[base] = make_uint2(*(uint32_t*)&p01, *(uint32_t*)&p23);
        }
    };

    if (!is_consumer) fill(0, blockIdx.x);
    __syncthreads();

    const int warp = tid >> 5;
    const int g    = lane >> 2;
    const int tig  = lane & 3;
    const int wm   = warp & 3;
    const int wn   = warp >> 2;

    const uint32_t offA = ldsmA_off(lane) + (uint32_t)(wm * 32 * PITCH * 2);
    const uint32_t offB = ldsmB_off(lane) + (uint32_t)(wn * 64 * PITCH * 2);
    const uint32_t wh_a = smem_u32(w_h) + offB;
    const uint32_t wl_a = smem_u32(w_l) + offB;

    int s = 0;
    for (int t = blockIdx.x; t < TILES; t += GRID, s++) {
        const int buf = s & 1;
        if (is_consumer) {
            const uint32_t x_a = smem_u32(xbuf + buf * TSZ) + offA;

            float acc[2][8][4];
            #pragma unroll
            for (int mt = 0; mt < 2; mt++)
                #pragma unroll
                for (int nt = 0; nt < 8; nt++)
                    #pragma unroll
                    for (int q = 0; q < 4; q++) acc[mt][nt][q] = 0.f;

            #pragma unroll
            for (int ks = 0; ks < 8; ks++) {
                const uint32_t kb = ks * 32;

                uint32_t a[2][4];
                #pragma unroll
                for (int mt = 0; mt < 2; mt++)
                    ldsm4(a[mt], x_a + mt * (16 * PITCH * 2) + kb);

                uint32_t b_h[8][2], b_l[8][2];
                #pragma unroll
                for (int np = 0; np < 4; np++) {
                    ldsm4(&b_h[2 * np][0], wh_a + np * (16 * PITCH * 2) + kb);
                    ldsm4(&b_l[2 * np][0], wl_a + np * (16 * PITCH * 2) + kb);
                }

                #pragma unroll
                for (int mt = 0; mt < 2; mt++)
                    #pragma unroll
                    for (int nt = 0; nt < 8; nt++) {
                        mma_f16(acc[mt][nt], a[mt], b_h[nt]);
                        mma_f16(acc[mt][nt], a[mt], b_l[nt]);
                    }
            }

            float p[2][2][2];
            #pragma unroll
            for (int mt = 0; mt < 2; mt++)
                #pragma unroll
                for (int r = 0; r < 2; r++) { p[mt][r][0] = 0.f; p[mt][r][1] = 0.f; }

            #pragma unroll
            for (int nt = 0; nt < 8; nt++) {
                int c0 = wn * 64 + nt * 8 + 2 * tig;
                float bb0 = s_b2[c0], bb1 = s_b2[c0 + 1];
                float w300 = s_w3[c0 * 2],       w310 = s_w3[c0 * 2 + 1];
                float w301 = s_w3[(c0 + 1) * 2], w311 = s_w3[(c0 + 1) * 2 + 1];
                #pragma unroll
                for (int mt = 0; mt < 2; mt++) {
                    float x00 = fmaxf(acc[mt][nt][0] + bb0, 0.f);
                    float x01 = fmaxf(acc[mt][nt][1] + bb1, 0.f);
                    float x10 = fmaxf(acc[mt][nt][2] + bb0, 0.f);
                    float x11 = fmaxf(acc[mt][nt][3] + bb1, 0.f);
                    p[mt][0][0] = fmaf(x00, w300, fmaf(x01, w301, p[mt][0][0]));
                    p[mt][0][1] = fmaf(x00, w310, fmaf(x01, w311, p[mt][0][1]));
                    p[mt][1][0] = fmaf(x10, w300, fmaf(x11, w301, p[mt][1][0]));
                    p[mt][1][1] = fmaf(x10, w310, fmaf(x11, w311, p[mt][1][1]));
                }
            }

            #pragma unroll
            for (int mt = 0; mt < 2; mt++)
                #pragma unroll
                for (int r = 0; r < 2; r++)
                    #pragma unroll
                    for (int o = 0; o < 2; o++) {
                        float v = p[mt][r][o];
                        v += __shfl_xor_sync(0xffffffffu, v, 1);
                        v += __shfl_xor_sync(0xffffffffu, v, 2);
                        p[mt][r][o] = v;
                    }

            if (tig == 0) {
                #pragma unroll
                for (int mt = 0; mt < 2; mt++) {
                    int r0 = wm * 32 + mt * 16 + g;
                    s_part[wn][r0][0]     = p[mt][0][0];
                    s_part[wn][r0][1]     = p[mt][0][1];
                    s_part[wn][r0 + 8][0] = p[mt][1][0];
                    s_part[wn][r0 + 8][1] = p[mt][1][1];
                }
            }
            asm volatile("bar.sync 1, 256;" ::: "memory");
            out[(size_t)t * 256 + tid] =
                s_part[0][tid >> 1][tid & 1] + s_part[1][tid >> 1][tid & 1] + s_b3[tid & 1];
        } else {
            int tn = t + GRID;
            if (tn < TILES) fill(buf ^ 1, tn);
        }
        __syncthreads();
    }
}

// ---------------------------------------------------------------------------
extern "C" void kernel_launch(void* const* d_in, const int* in_sizes, int n_in,
                              void* d_out, int out_size) {
    const float* h   = (const float*)d_in[0];
    const int*   src = (const int*)d_in[1];
    const int*   dst = (const int*)d_in[2];
    const float* W1  = (const float*)d_in[3];
    const float* b1  = (const float*)d_in[4];
    const float* W2  = (const float*)d_in[5];
    const float* b2  = (const float*)d_in[6];
    const float* W3  = (const float*)d_in[7];
    const float* b3  = (const float*)d_in[8];
    float* out = (float*)d_out;

    const int node_smem = 6 * TSZ * (int)sizeof(__nv_bfloat16);  // 208896
    const int edge_smem = 4 * TSZ * (int)sizeof(__half);         // 139264
    cudaFuncSetAttribute(node_kernel, cudaFuncAttributeMaxDynamicSharedMemorySize, node_smem);
    cudaFuncSetAttribute(edge_kernel, cudaFuncAttributeMaxDynamicSharedMemorySize, edge_smem);

    node_kernel<<<dim3(GRID, 2), 384, node_smem>>>(h, W1, b1);
    edge_kernel<<<GRID, 384, edge_smem>>>(src, dst, W2, b2, W3, b3, out);
}

// round 11
// speedup vs baseline: 1.2876x; 1.0407x over previous
#include <cuda_runtime.h>
#include <cuda_bf16.h>
#include <cuda_fp16.h>
#include <cstdint>

#define N_NODES 100000
#define N_EDGES 800000
#define F 128
#define HID 128
#define PITCH 136            // elems per row in shared tiles (conflict-free LDSM)
#define TSZ (128 * PITCH)
#define TILES (N_EDGES / 128)
#define NT_TILES ((N_NODES + 127) / 128)
#define GRID 148

// Precomputed per-node tables: A = h @ W1[0:128,:] + b1,  B = h @ W1[128:256,:]
__device__ float d_AB[2u * N_NODES * F];

// ---------------------------------------------------------------------------
__device__ __forceinline__ void mma_f16(float* c, const uint32_t* a, const uint32_t* b) {
    asm volatile(
        "mma.sync.aligned.m16n8k16.row.col.f32.f16.f16.f32 "
        "{%0,%1,%2,%3}, {%4,%5,%6,%7}, {%8,%9}, {%0,%1,%2,%3};\n"
        : "+f"(c[0]), "+f"(c[1]), "+f"(c[2]), "+f"(c[3])
        : "r"(a[0]), "r"(a[1]), "r"(a[2]), "r"(a[3]), "r"(b[0]), "r"(b[1]));
}

__device__ __forceinline__ void ldsm4(uint32_t* r, uint32_t addr) {
    asm volatile("ldmatrix.sync.aligned.m8n8.x4.shared.b16 {%0,%1,%2,%3}, [%4];"
                 : "=r"(r[0]), "=r"(r[1]), "=r"(r[2]), "=r"(r[3]) : "r"(addr));
}

__device__ __forceinline__ void split_f16(float x, __half& hi, __half& lo) {
    hi = __float2half(x);
    lo = __float2half(x - __half2float(hi));
}

__device__ __forceinline__ uint32_t smem_u32(const void* p) {
    uint32_t a;
    asm("{ .reg .u64 t; cvta.to.shared.u64 t, %1; cvt.u32.u64 %0, t; }" : "=r"(a) : "l"(p));
    return a;
}

// Per-lane LDSM byte offsets within a [row][PITCH] 16-bit tile.
__device__ __forceinline__ uint32_t ldsmA_off(int lane) {
    return (uint32_t)(((lane & 15) * PITCH + ((lane >> 4) * 8)) * 2);
}
__device__ __forceinline__ uint32_t ldsmB_off(int lane) {
    return (uint32_t)((((lane & 7) + ((lane & 16) >> 1)) * PITCH + ((lane & 8) ? 8 : 0)) * 2);
}

// ---------------------------------------------------------------------------
// Kernel 1: node GEMM — persistent, warp-specialized, fp16 2-pass.
// x = fp16(h); W1 slice split w_h + w_l. grid (148, 2): y = part.
// ---------------------------------------------------------------------------
__global__ void __launch_bounds__(384, 1)
node_kernel(const float* __restrict__ h,
            const float* __restrict__ W1,
            const float* __restrict__ b1) {
    extern __shared__ __half smh[];
    __half* w_h  = smh;                  // [n][k] transposed fp16 hi
    __half* w_l  = smh + TSZ;            // fp16 residual
    __half* xbuf = smh + 2 * TSZ;        // 2 buffers, plain fp16

    __shared__ float s_b1[128];

    const int tid  = threadIdx.x;
    const int lane = tid & 31;
    const int part = blockIdx.y;

    const float* Wp = W1 + part * F * HID;
    for (int idx = tid; idx < 128 * 128; idx += 384) {
        int k = idx >> 7, n = idx & 127;
        float w = Wp[idx];
        __half wh, wl;
        split_f16(w, wh, wl);
        w_h[n * PITCH + k] = wh;
        w_l[n * PITCH + k] = wl;
    }
    if (tid < 128) s_b1[tid] = (part == 0) ? b1[tid] : 0.f;
    __syncthreads();

    const bool is_consumer = tid < 256;
    const int  ptid = tid - 256;

    const float4* h4 = (const float4*)h;
    auto fill = [&](int buf, int t) {
        __half* x = xbuf + buf * TSZ;
        const int r0 = t * 128;
        #pragma unroll
        for (int i = 0; i < 32; i++) {
            int lin = ptid + 128 * i;
            int e = lin >> 5, v = lin & 31;
            int r = r0 + e;
            float4 a = make_float4(0.f, 0.f, 0.f, 0.f);
            if (r < N_NODES) a = h4[(size_t)r * 32 + v];
            __half2 p01 = __floats2half2_rn(a.x, a.y);
            __half2 p23 = __floats2half2_rn(a.z, a.w);
            int base = e * PITCH + v * 4;
            *(uint2*)&x[base] = make_uint2(*(uint32_t*)&p01, *(uint32_t*)&p23);
        }
    };

    if (!is_consumer) fill(0, blockIdx.x);
    __syncthreads();

    const int warp = tid >> 5;
    const int g    = lane >> 2;
    const int tig  = lane & 3;
    const int wm   = warp & 3;
    const int wn   = warp >> 2;

    const uint32_t offA = ldsmA_off(lane) + (uint32_t)(wm * 32 * PITCH * 2);
    const uint32_t offB = ldsmB_off(lane) + (uint32_t)(wn * 64 * PITCH * 2);
    const uint32_t wh_a = smem_u32(w_h) + offB;
    const uint32_t wl_a = smem_u32(w_l) + offB;

    float* table = d_AB + (size_t)part * N_NODES * F;

    int s = 0;
    for (int t = blockIdx.x; t < NT_TILES; t += GRID, s++) {
        const int buf = s & 1;
        if (is_consumer) {
            const uint32_t x_a = smem_u32(xbuf + buf * TSZ) + offA;

            float acc[2][8][4];
            #pragma unroll
            for (int mt = 0; mt < 2; mt++)
                #pragma unroll
                for (int nt = 0; nt < 8; nt++)
                    #pragma unroll
                    for (int q = 0; q < 4; q++) acc[mt][nt][q] = 0.f;

            #pragma unroll
            for (int ks = 0; ks < 8; ks++) {
                const uint32_t kb = ks * 32;

                uint32_t a[2][4];
                #pragma unroll
                for (int mt = 0; mt < 2; mt++)
                    ldsm4(a[mt], x_a + mt * (16 * PITCH * 2) + kb);

                uint32_t b_h[8][2], b_l[8][2];
                #pragma unroll
                for (int np = 0; np < 4; np++) {
                    ldsm4(&b_h[2 * np][0], wh_a + np * (16 * PITCH * 2) + kb);
                    ldsm4(&b_l[2 * np][0], wl_a + np * (16 * PITCH * 2) + kb);
                }

                #pragma unroll
                for (int mt = 0; mt < 2; mt++)
                    #pragma unroll
                    for (int nt = 0; nt < 8; nt++) {
                        mma_f16(acc[mt][nt], a[mt], b_h[nt]);
                        mma_f16(acc[mt][nt], a[mt], b_l[nt]);
                    }
            }

            const int r_base = t * 128 + wm * 32 + g;
            #pragma unroll
            for (int mt = 0; mt < 2; mt++) {
                #pragma unroll
                for (int r = 0; r < 2; r++) {
                    int row = r_base + mt * 16 + r * 8;
                    if (row < N_NODES) {
                        float* rp = table + (size_t)row * 128 + wn * 64;
                        #pragma unroll
                        for (int nt = 0; nt < 8; nt++) {
                            int c = nt * 8 + 2 * tig;
                            float2 v;
                            v.x = acc[mt][nt][2 * r]     + s_b1[wn * 64 + c];
                            v.y = acc[mt][nt][2 * r + 1] + s_b1[wn * 64 + c + 1];
                            *(float2*)(rp + c) = v;
                        }
                    }
                }
            }
        } else {
            int tn = t + GRID;
            if (tn < NT_TILES) fill(buf ^ 1, tn);
        }
        __syncthreads();
    }
}

// ---------------------------------------------------------------------------
// Kernel 2: edge kernel — fp16 2-pass (unchanged from R10).
// ---------------------------------------------------------------------------
__global__ void __launch_bounds__(384, 1)
edge_kernel(const int* __restrict__ src,
            const int* __restrict__ dst,
            const float* __restrict__ W2,
            const float* __restrict__ b2,
            const float* __restrict__ W3,
            const float* __restrict__ b3,
            float* __restrict__ out) {
    extern __shared__ __half smh[];
    __half* w_h  = smh;
    __half* w_l  = smh + TSZ;
    __half* xbuf = smh + 2 * TSZ;

    __shared__ float s_b2[128];
    __shared__ float s_w3[256];
    __shared__ float s_b3[2];
    __shared__ float s_part[2][128][2];

    const int tid  = threadIdx.x;
    const int lane = tid & 31;

    for (int idx = tid; idx < 128 * 128; idx += 384) {
        int k = idx >> 7, n = idx & 127;
        float w = W2[idx];
        __half wh, wl;
        split_f16(w, wh, wl);
        w_h[n * PITCH + k] = wh;
        w_l[n * PITCH + k] = wl;
    }
    if (tid < 128) s_b2[tid] = b2[tid];
    if (tid < 256) s_w3[tid] = W3[tid];
    if (tid < 2)   s_b3[tid] = b3[tid];
    __syncthreads();

    const float4* A4 = (const float4*)d_AB;
    const float4* B4 = (const float4*)(d_AB + (size_t)N_NODES * F);
    const bool is_consumer = tid < 256;
    const int  ptid = tid - 256;

    auto fill = [&](int buf, int t) {
        __half* x = xbuf + buf * TSZ;
        const int e0 = t * 128;
        #pragma unroll
        for (int i = 0; i < 32; i++) {
            int lin = ptid + 128 * i;
            int e = lin >> 5, v = lin & 31;
            int si = src[e0 + e], di = dst[e0 + e];
            float4 a = A4[(size_t)si * 32 + v];
            float4 b = B4[(size_t)di * 32 + v];
            __half2 p01 = __floats2half2_rn(fmaxf(a.x + b.x, 0.f), fmaxf(a.y + b.y, 0.f));
            __half2 p23 = __floats2half2_rn(fmaxf(a.z + b.z, 0.f), fmaxf(a.w + b.w, 0.f));
            int base = e * PITCH + v * 4;
            *(uint2*)&x[base] = make_uint2(*(uint32_t*)&p01, *(uint32_t*)&p23);
        }
    };

    if (!is_consumer) fill(0, blockIdx.x);
    __syncthreads();

    const int warp = tid >> 5;
    const int g    = lane >> 2;
    const int tig  = lane & 3;
    const int wm   = warp & 3;
    const int wn   = warp >> 2;

    const uint32_t offA = ldsmA_off(lane) + (uint32_t)(wm * 32 * PITCH * 2);
    const uint32_t offB = ldsmB_off(lane) + (uint32_t)(wn * 64 * PITCH * 2);
    const uint32_t wh_a = smem_u32(w_h) + offB;
    const uint32_t wl_a = smem_u32(w_l) + offB;

    int s = 0;
    for (int t = blockIdx.x; t < TILES; t += GRID, s++) {
        const int buf = s & 1;
        if (is_consumer) {
            const uint32_t x_a = smem_u32(xbuf + buf * TSZ) + offA;

            float acc[2][8][4];
            #pragma unroll
            for (int mt = 0; mt < 2; mt++)
                #pragma unroll
                for (int nt = 0; nt < 8; nt++)
                    #pragma unroll
                    for (int q = 0; q < 4; q++) acc[mt][nt][q] = 0.f;

            #pragma unroll
            for (int ks = 0; ks < 8; ks++) {
                const uint32_t kb = ks * 32;

                uint32_t a[2][4];
                #pragma unroll
                for (int mt = 0; mt < 2; mt++)
                    ldsm4(a[mt], x_a + mt * (16 * PITCH * 2) + kb);

                uint32_t b_h[8][2], b_l[8][2];
                #pragma unroll
                for (int np = 0; np < 4; np++) {
                    ldsm4(&b_h[2 * np][0], wh_a + np * (16 * PITCH * 2) + kb);
                    ldsm4(&b_l[2 * np][0], wl_a + np * (16 * PITCH * 2) + kb);
                }

                #pragma unroll
                for (int mt = 0; mt < 2; mt++)
                    #pragma unroll
                    for (int nt = 0; nt < 8; nt++) {
                        mma_f16(acc[mt][nt], a[mt], b_h[nt]);
                        mma_f16(acc[mt][nt], a[mt], b_l[nt]);
                    }
            }

            float p[2][2][2];
            #pragma unroll
            for (int mt = 0; mt < 2; mt++)
                #pragma unroll
                for (int r = 0; r < 2; r++) { p[mt][r][0] = 0.f; p[mt][r][1] = 0.f; }

            #pragma unroll
            for (int nt = 0; nt < 8; nt++) {
                int c0 = wn * 64 + nt * 8 + 2 * tig;
                float bb0 = s_b2[c0], bb1 = s_b2[c0 + 1];
                float w300 = s_w3[c0 * 2],       w310 = s_w3[c0 * 2 + 1];
                float w301 = s_w3[(c0 + 1) * 2], w311 = s_w3[(c0 + 1) * 2 + 1];
                #pragma unroll
                for (int mt = 0; mt < 2; mt++) {
                    float x00 = fmaxf(acc[mt][nt][0] + bb0, 0.f);
                    float x01 = fmaxf(acc[mt][nt][1] + bb1, 0.f);
                    float x10 = fmaxf(acc[mt][nt][2] + bb0, 0.f);
                    float x11 = fmaxf(acc[mt][nt][3] + bb1, 0.f);
                    p[mt][0][0] = fmaf(x00, w300, fmaf(x01, w301, p[mt][0][0]));
                    p[mt][0][1] = fmaf(x00, w310, fmaf(x01, w311, p[mt][0][1]));
                    p[mt][1][0] = fmaf(x10, w300, fmaf(x11, w301, p[mt][1][0]));
                    p[mt][1][1] = fmaf(x10, w310, fmaf(x11, w311, p[mt][1][1]));
                }
            }

            #pragma unroll
            for (int mt = 0; mt < 2; mt++)
                #pragma unroll
                for (int r = 0; r < 2; r++)
                    #pragma unroll
                    for (int o = 0; o < 2; o++) {
                        float v = p[mt][r][o];
                        v += __shfl_xor_sync(0xffffffffu, v, 1);
                        v += __shfl_xor_sync(0xffffffffu, v, 2);
                        p[mt][r][o] = v;
                    }

            if (tig == 0) {
                #pragma unroll
                for (int mt = 0; mt < 2; mt++) {
                    int r0 = wm * 32 + mt * 16 + g;
                    s_part[wn][r0][0]     = p[mt][0][0];
                    s_part[wn][r0][1]     = p[mt][0][1];
                    s_part[wn][r0 + 8][0] = p[mt][1][0];
                    s_part[wn][r0 + 8][1] = p[mt][1][1];
                }
            }
            asm volatile("bar.sync 1, 256;" ::: "memory");
            out[(size_t)t * 256 + tid] =
                s_part[0][tid >> 1][tid & 1] + s_part[1][tid >> 1][tid & 1] + s_b3[tid & 1];
        } else {
            int tn = t + GRID;
            if (tn < TILES) fill(buf ^ 1, tn);
        }
        __syncthreads();
    }
}

// ---------------------------------------------------------------------------
extern "C" void kernel_launch(void* const* d_in, const int* in_sizes, int n_in,
                              void* d_out, int out_size) {
    const float* h   = (const float*)d_in[0];
    const int*   src = (const int*)d_in[1];
    const int*   dst = (const int*)d_in[2];
    const float* W1  = (const float*)d_in[3];
    const float* b1  = (const float*)d_in[4];
    const float* W2  = (const float*)d_in[5];
    const float* b2  = (const float*)d_in[6];
    const float* W3  = (const float*)d_in[7];
    const float* b3  = (const float*)d_in[8];
    float* out = (float*)d_out;

    const int smem = 4 * TSZ * (int)sizeof(__half);   // 139264
    cudaFuncSetAttribute(node_kernel, cudaFuncAttributeMaxDynamicSharedMemorySize, smem);
    cudaFuncSetAttribute(edge_kernel, cudaFuncAttributeMaxDynamicSharedMemorySize, smem);

    node_kernel<<<dim3(GRID, 2), 384, smem>>>(h, W1, b1);
    edge_kernel<<<GRID, 384, smem>>>(src, dst, W2, b2, W3, b3, out);
}